// round 16
// baseline (speedup 1.0000x reference)
#include <cuda_runtime.h>
#include <cuda_fp16.h>
#include <math.h>
#include <stdint.h>

#define HH 512
#define WW 512
#define NP (HH*WW)
#define PW 517                      // padded dim (2 left/top, 3 right/bottom)

// ---------------- scratch (device globals) ---------------------------------
__device__ __align__(16) __half g_xp[PW*PW*64];        // input NHWC fp16, zero-padded
__device__ __align__(16) __half g_h1p[PW*PW*64];       // layer-1 out NHWC fp16, zero-padded
__device__ __align__(16) __half g_wdb[2][9][64*64];    // dcn W fp16: [layer][tap][SWZ(c*128+oc*2)]
__device__ __align__(16) __half g_wob[2][9][64*64];    // off W fp16, padded to 64 oc
__device__ float g_bnscale[2][64];
__device__ float g_bnshift[2][64];

// ---------------- smem layout (bytes) ----------------------------------------
#define SLAB_PX   130
#define P1_B0     50176
#define P1_B1     58368
#define P2_A0     0
#define P2_A1     16384
#define P2_B0     32768
#define P2_B1     40960
#define OFFS_OFF  66560
#define LAYER_SMEM 75776

// ---------------- helpers ----------------------------------------------------
__device__ __forceinline__ uint32_t smem_u32(const void* p) {
    uint32_t a;
    asm("{ .reg .u64 t; cvta.to.shared.u64 t, %1; cvt.u32.u64 %0, t; }" : "=r"(a) : "l"(p));
    return a;
}
#define SWZ(b) ((b) ^ (((b) >> 3) & 0x70))

#define CP_ASYNC16(dst, src) \
    asm volatile("cp.async.cg.shared.global [%0], [%1], 16;" :: "r"(dst), "l"(src))
#define CP_COMMIT()  asm volatile("cp.async.commit_group;")
#define CP_WAIT0()   asm volatile("cp.async.wait_group 0;")

#define LDSM4(r, addr) \
    asm volatile("ldmatrix.sync.aligned.m8n8.x4.shared.b16 {%0,%1,%2,%3}, [%4];" \
        : "=r"((r)[0]), "=r"((r)[1]), "=r"((r)[2]), "=r"((r)[3]) : "r"(addr))
#define LDSM4T(r, addr) \
    asm volatile("ldmatrix.sync.aligned.m8n8.x4.trans.shared.b16 {%0,%1,%2,%3}, [%4];" \
        : "=r"((r)[0]), "=r"((r)[1]), "=r"((r)[2]), "=r"((r)[3]) : "r"(addr))
#define MMA(d, a, b0_, b1_) \
    asm volatile("mma.sync.aligned.m16n8k16.row.col.f32.f16.f16.f32 " \
        "{%0,%1,%2,%3}, {%4,%5,%6,%7}, {%8,%9}, {%0,%1,%2,%3};" \
        : "+f"((d)[0]), "+f"((d)[1]), "+f"((d)[2]), "+f"((d)[3]) \
        : "r"((a)[0]), "r"((a)[1]), "r"((a)[2]), "r"((a)[3]), "r"(b0_), "r"(b1_))

// ---- packed f32x2 (sm_100+ base PTX; FFMA2 in SASS) ----
__device__ __forceinline__ uint64_t f2_pack(float lo, float hi) {
    uint64_t r; asm("mov.b64 %0, {%1, %2};" : "=l"(r) : "f"(lo), "f"(hi)); return r;
}
__device__ __forceinline__ uint64_t f2_mul(uint64_t a, uint64_t b) {
    uint64_t r; asm("mul.rn.f32x2 %0, %1, %2;" : "=l"(r) : "l"(a), "l"(b)); return r;
}
__device__ __forceinline__ uint64_t f2_fma(uint64_t a, uint64_t b, uint64_t c) {
    uint64_t r; asm("fma.rn.f32x2 %0, %1, %2, %3;" : "=l"(r) : "l"(a), "l"(b), "l"(c)); return r;
}
__device__ __forceinline__ void f2_unpack(uint64_t v, float& lo, float& hi) {
    asm("mov.b64 {%0, %1}, %2;" : "=f"(lo), "=f"(hi) : "l"(v));
}
__device__ __forceinline__ uint64_t h2_to_f2(uint32_t h) {
    float2 f = __half22float2(*(const __half2*)&h);
    return f2_pack(f.x, f.y);
}

// ---------------- GEMM one tap (dcn, 4M x 2N warps, single-pass B, 64 oc) ---
__device__ __forceinline__ void gemm_tap_dcn(uint32_t sAb, uint32_t sBb, int lid,
                                             int mwarp, int nwarp, float acc[2][4][4]) {
    #pragma unroll
    for (int kb = 0; kb < 4; kb++) {
        uint32_t ah[2][4];
        #pragma unroll
        for (int mb = 0; mb < 2; mb++) {
            int row = mwarp*32 + mb*16 + (lid & 15);
            uint32_t a = sAb + SWZ((uint32_t)(row*128 + (kb*16 + (lid>>4)*8)*2));
            LDSM4(ah[mb], a);
        }
        #pragma unroll
        for (int nb2 = 0; nb2 < 2; nb2++) {
            int k = kb*16 + (lid & 15);
            int n = nwarp*32 + nb2*16 + (lid>>4)*8;
            uint32_t b = sBb + SWZ((uint32_t)(k*128 + n*2));
            uint32_t bh[4];
            LDSM4T(bh, b);
            #pragma unroll
            for (int mb = 0; mb < 2; mb++) {
                MMA(acc[mb][2*nb2],   ah[mb], bh[0], bh[1]);
                MMA(acc[mb][2*nb2+1], ah[mb], bh[2], bh[3]);
            }
        }
    }
}

// ---------------- GEMM one tap (offconv from slab, 32 oc) -------------------
__device__ __forceinline__ void gemm_tap_off_slab(uint32_t sbase, int ky, int kx,
                                                  uint32_t sBb, int lid,
                                                  int mwarp, int nwarp, float acc[2][2][4]) {
    const int srbase = ky*SLAB_PX + kx;
    #pragma unroll
    for (int kb = 0; kb < 4; kb++) {
        uint32_t ah[2][4];
        #pragma unroll
        for (int mb = 0; mb < 2; mb++) {
            int row = srbase + mwarp*32 + mb*16 + (lid & 15);
            uint32_t a = sbase + SWZ((uint32_t)(row*128 + (kb*16 + (lid>>4)*8)*2));
            LDSM4(ah[mb], a);
        }
        int k = kb*16 + (lid & 15);
        int n = nwarp*16 + (lid>>4)*8;
        uint32_t b = sBb + SWZ((uint32_t)(k*128 + n*2));
        uint32_t bh[4];
        LDSM4T(bh, b);
        #pragma unroll
        for (int mb = 0; mb < 2; mb++) {
            MMA(acc[mb][0], ah[mb], bh[0], bh[1]);
            MMA(acc[mb][1], ah[mb], bh[2], bh[3]);
        }
    }
}

// stage tap weights (8KB fp16) via cp.async
__device__ __forceinline__ void stage_b8(const __half* __restrict__ wsrc, int k,
                                         uint32_t sBb, int t) {
    const char* src = (const char*)(wsrc + (size_t)k * 4096);
    #pragma unroll
    for (int i = 0; i < 2; i++)
        CP_ASYNC16(sBb + (uint32_t)(i*256 + t)*16, src + (size_t)(i*256 + t)*16);
}

// stage the 3x130-pixel input slab, swizzled (48.75KB) via cp.async
__device__ __forceinline__ void stage_slab(const __half* __restrict__ in,
                                           int by, int x0, uint32_t sbase, int t) {
    for (int idx = t; idx < 3*SLAB_PX*8; idx += 256) {
        int pix = idx >> 3, sub = idx & 7;
        int r = pix / SLAB_PX, p = pix % SLAB_PX;
        const char* src = (const char*)(in + ((size_t)((by+1+r)*PW + (x0+1+p)))*64) + sub*16;
        uint32_t dst = sbase + SWZ((uint32_t)((r*SLAB_PX + p)*128 + sub*16));
        CP_ASYNC16(dst, src);
    }
}

// bilinear sample one tap; f32x2 packed weighted sum (2 channels per op)
__device__ __forceinline__ void sample_dcn(const __half* __restrict__ in,
                                           const float* __restrict__ offs,
                                           int by, int x0, int ky, int kx,
                                           int koff, char* sm, uint32_t abuf,
                                           const int* pxv, const uint32_t* aoff,
                                           int ch8) {
    #pragma unroll
    for (int it = 0; it < 4; it++) {
        int px = pxv[it];
        float2 od = *(const float2*)(offs + px*18 + koff);
        float py  = (float)(by + ky) + od.x;
        float pxf = (float)(x0 + px + kx) + od.y;
        float fy = floorf(py), fx = floorf(pxf);
        float wy = py - fy, wx = pxf - fx;
        int yi = min(max((int)fy, -2), 513);
        int xi = min(max((int)fx, -2), 513);
        float w00 = (1.f - wy)*(1.f - wx);
        float w01 = (1.f - wy)*wx;
        float w10 = wy*(1.f - wx);
        float w11 = wy*wx;
        uint64_t w00p = f2_pack(w00, w00);
        uint64_t w01p = f2_pack(w01, w01);
        uint64_t w10p = f2_pack(w10, w10);
        uint64_t w11p = f2_pack(w11, w11);
        const __half* b00 = in + ((size_t)((yi+2)*PW + (xi+2)))*64 + ch8*8;
        const __half* b10 = b00 + (size_t)PW*64;
        uint4 r00 = *(const uint4*)b00;
        uint4 r01 = *(const uint4*)(b00 + 64);
        uint4 r10 = *(const uint4*)b10;
        uint4 r11 = *(const uint4*)(b10 + 64);
        uint4 outv;
        const uint32_t* p00 = &r00.x;
        const uint32_t* p01 = &r01.x;
        const uint32_t* p10 = &r10.x;
        const uint32_t* p11 = &r11.x;
        uint32_t* po = &outv.x;
        #pragma unroll
        for (int j = 0; j < 4; j++) {
            uint64_t s = f2_mul(h2_to_f2(p00[j]), w00p);
            s = f2_fma(h2_to_f2(p01[j]), w01p, s);
            s = f2_fma(h2_to_f2(p10[j]), w10p, s);
            s = f2_fma(h2_to_f2(p11[j]), w11p, s);
            float lo, hi;
            f2_unpack(s, lo, hi);
            __half2 h = __floats2half2_rn(lo, hi);
            po[j] = *(const uint32_t*)&h;
        }
        *(uint4*)(sm + abuf + aoff[it]) = outv;
    }
}

// ---------------- prep: weight swizzle + BN folding --------------------------
__global__ void prep_kernel(
    const float* __restrict__ w1o, const float* __restrict__ w2o,
    const float* __restrict__ wd1, const float* __restrict__ wd2,
    const float* __restrict__ db1, const float* __restrict__ db2,
    const float* __restrict__ g1, const float* __restrict__ b1,
    const float* __restrict__ m1, const float* __restrict__ v1,
    const float* __restrict__ g2, const float* __restrict__ b2,
    const float* __restrict__ m2, const float* __restrict__ v2)
{
    int idx = blockIdx.x * blockDim.x + threadIdx.x;
    int nth = gridDim.x * blockDim.x;
    for (int i = idx; i < 2*9*64*64; i += nth) {
        int layer = i / 36864, r = i % 36864;
        int k = r / 4096, rr = r & 4095;
        int c = rr >> 6, oc = rr & 63;
        uint32_t sidx = SWZ((uint32_t)(c*128 + oc*2)) >> 1;
        {
            float val = (layer ? wd2 : wd1)[(oc*64 + c)*9 + k];
            g_wdb[layer][k][sidx] = __float2half_rn(val);
        }
        {
            float val = (oc < 18) ? (layer ? w2o : w1o)[(oc*64 + c)*9 + k] : 0.f;
            g_wob[layer][k][sidx] = __float2half_rn(val);
        }
    }
    if (idx < 64) {
        float s = g1[idx] * rsqrtf(v1[idx] + 1e-5f);
        g_bnscale[0][idx] = s;
        g_bnshift[0][idx] = b1[idx] - m1[idx]*s + db1[idx]*s;
        float s2 = g2[idx] * rsqrtf(v2[idx] + 1e-5f);
        g_bnscale[1][idx] = s2;
        g_bnshift[1][idx] = b2[idx] - m2[idx]*s2 + db2[idx]*s2;
    }
}

// ---------------- NCHW f32 -> padded NHWC fp16 (+border zeroing) -------------
__global__ void __launch_bounds__(256) transpose_kernel(const float* __restrict__ x) {
    __shared__ float tile[64][65];
    int b = blockIdx.x;
    int t = threadIdx.x;
    if (b >= 4096) {
        int idx = (b - 4096)*256 + t;
        if (idx >= 5145) return;
        int r, c;
        if (idx < 2585) {                   // 5 full rows: 0,1,514,515,516
            int rr = idx / 517;
            r = (rr < 2) ? rr : (512 + rr);
            c = idx % 517;
        } else {
            int j = idx - 2585;
            r = 2 + j / 5;
            int jc = j % 5;
            c = (jc < 2) ? jc : (512 + jc);
        }
        uint4 z = make_uint4(0u, 0u, 0u, 0u);
        uint4* p0 = (uint4*)(g_xp  + ((size_t)(r*PW + c))*64);
        uint4* p1 = (uint4*)(g_h1p + ((size_t)(r*PW + c))*64);
        #pragma unroll
        for (int i = 0; i < 8; i++) { p0[i] = z; p1[i] = z; }
        return;
    }
    int p0 = b * 64;
    #pragma unroll
    for (int i = 0; i < 16; i++) {
        int idx = i*256 + t;
        int c = idx >> 6, pl = idx & 63;
        tile[c][pl] = x[c*NP + p0 + pl];
    }
    __syncthreads();
    int y = p0 / WW, xb = p0 % WW;
    __half* dst = g_xp + ((size_t)((y+2)*PW + xb + 2))*64;
    #pragma unroll
    for (int i = 0; i < 8; i++) {
        int idx = i*512 + t*2;          // pairs of channels
        int pl = idx >> 6, c = idx & 63;
        __half2 h = __floats2half2_rn(tile[c][pl], tile[c+1][pl]);
        *(__half2*)(dst + (size_t)pl*64 + c) = h;
    }
}

// ---------------- fused layer: offconv(slab) -> deform conv -> BN/ReLU (+1x1)
template<int FUSE>
__global__ void __launch_bounds__(256, 3) layer_kernel(int layer,
    const float* __restrict__ obias,
    const float* __restrict__ w1x1, const float* __restrict__ b1x1,
    float* __restrict__ out_f)
{
    extern __shared__ char sm[];
    const uint32_t sbase = smem_u32(sm);
    float* offs = (float*)(sm + OFFS_OFF);
    const __half* __restrict__ in = layer ? g_h1p : g_xp;
    const __half* __restrict__ wo = &g_wob[layer][0][0];
    const __half* __restrict__ wd = &g_wdb[layer][0][0];
    const float* __restrict__ scl = g_bnscale[layer];
    const float* __restrict__ shf = g_bnshift[layer];
    const int t = threadIdx.x;
    const int wid = t >> 5, lid = t & 31;
    const int mwarp = wid & 3, nwarp = wid >> 2;
    const int by = blockIdx.x >> 2;
    const int x0 = (blockIdx.x & 3) * 128;
    const int p0 = by*WW + x0;
    const int ch8 = lid & 7;
    const int pxq = lid >> 3;

    int pxv[4];
    uint32_t aoff[4];
    #pragma unroll
    for (int it = 0; it < 4; it++) {
        pxv[it] = it*32 + wid*4 + pxq;
        aoff[it] = SWZ((uint32_t)(pxv[it]*128 + ch8*16));
    }

    // ================= phase 1: offset conv from input slab =================
    {
        stage_slab(in, by, x0, sbase, t);
        stage_b8(wo, 0, sbase + P1_B0, t);
        CP_COMMIT();
        CP_WAIT0();
        __syncthreads();

        float acc[2][2][4] = {};
        #pragma unroll
        for (int k = 0; k < 9; k++) {
            uint32_t cbb = (k & 1) ? P1_B1 : P1_B0;
            if (k < 8) {
                stage_b8(wo, k+1, sbase + ((k & 1) ? P1_B0 : P1_B1), t);
                CP_COMMIT();
            }
            gemm_tap_off_slab(sbase, k/3, k%3, sbase + cbb, lid, mwarp, nwarp, acc);
            CP_WAIT0();
            __syncthreads();
        }
        // overlap: stage phase-2 tap-0 B into the now-dead slab region
        stage_b8(wd, 0, sbase + P2_B0, t);
        CP_COMMIT();
        // epilogue -> smem offs (with bias)
        #pragma unroll
        for (int mb = 0; mb < 2; mb++) {
            int row = mwarp*32 + mb*16 + (lid >> 2);
            #pragma unroll
            for (int nb = 0; nb < 2; nb++) {
                int colb = nwarp*16 + nb*8 + (lid & 3)*2;
                if (colb < 18) {
                    float b0 = obias[colb], b1v = obias[colb+1];
                    offs[row*18 + colb]         = acc[mb][nb][0] + b0;
                    offs[row*18 + colb + 1]     = acc[mb][nb][1] + b1v;
                    offs[(row+8)*18 + colb]     = acc[mb][nb][2] + b0;
                    offs[(row+8)*18 + colb + 1] = acc[mb][nb][3] + b1v;
                }
            }
        }
        __syncthreads();
    }

    // ================= phase 2: deformable conv (single-pass B) =============
    sample_dcn(in, offs, by, x0, -1, -1, 0, sm, P2_A0, pxv, aoff, ch8);
    CP_WAIT0();
    __syncthreads();

    float acc[2][4][4] = {};
    #pragma unroll
    for (int k = 0; k < 9; k++) {
        uint32_t cab = (k & 1) ? P2_A1 : P2_A0;
        uint32_t cbb = (k & 1) ? P2_B1 : P2_B0;
        if (k < 8) {
            uint32_t nab = (k & 1) ? P2_A0 : P2_A1;
            uint32_t nbb = (k & 1) ? P2_B0 : P2_B1;
            stage_b8(wd, k+1, sbase + nbb, t);
            CP_COMMIT();
            sample_dcn(in, offs, by, x0, (k+1)/3 - 1, (k+1)%3 - 1, 2*(k+1),
                       sm, nab, pxv, aoff, ch8);
        }
        gemm_tap_dcn(sbase + cab, sbase + cbb, lid, mwarp, nwarp, acc);
        CP_WAIT0();
        __syncthreads();
    }

    if (!FUSE) {
        __half* dstbase = g_h1p + ((size_t)((by+2)*PW + x0 + 2))*64;
        #pragma unroll
        for (int mb = 0; mb < 2; mb++) {
            int row = mwarp*32 + mb*16 + (lid >> 2);
            #pragma unroll
            for (int nb = 0; nb < 4; nb++) {
                int colb = nwarp*32 + nb*8 + (lid & 3)*2;
                float s0 = scl[colb], s1 = scl[colb+1];
                float h0 = shf[colb], h1v = shf[colb+1];
                float v00 = fmaxf(acc[mb][nb][0]*s0 + h0, 0.f);
                float v01 = fmaxf(acc[mb][nb][1]*s1 + h1v, 0.f);
                float v10 = fmaxf(acc[mb][nb][2]*s0 + h0, 0.f);
                float v11 = fmaxf(acc[mb][nb][3]*s1 + h1v, 0.f);
                *(__half2*)(dstbase + (size_t)row*64 + colb)       = __floats2half2_rn(v00, v01);
                *(__half2*)(dstbase + (size_t)(row + 8)*64 + colb) = __floats2half2_rn(v10, v11);
            }
        }
    } else {
        float pa[2] = {0.f, 0.f}, pb[2] = {0.f, 0.f};
        #pragma unroll
        for (int mb = 0; mb < 2; mb++) {
            #pragma unroll
            for (int nb = 0; nb < 4; nb++) {
                int colb = nwarp*32 + nb*8 + (lid & 3)*2;
                float s0 = scl[colb], s1 = scl[colb+1];
                float h0 = shf[colb], h1v = shf[colb+1];
                float w0 = w1x1[colb], w1 = w1x1[colb+1];
                float v00 = fmaxf(acc[mb][nb][0]*s0 + h0, 0.f);
                float v01 = fmaxf(acc[mb][nb][1]*s1 + h1v, 0.f);
                float v10 = fmaxf(acc[mb][nb][2]*s0 + h0, 0.f);
                float v11 = fmaxf(acc[mb][nb][3]*s1 + h1v, 0.f);
                pa[mb] += v00*w0 + v01*w1;
                pb[mb] += v10*w0 + v11*w1;
            }
            pa[mb] += __shfl_xor_sync(0xffffffffu, pa[mb], 1);
            pa[mb] += __shfl_xor_sync(0xffffffffu, pa[mb], 2);
            pb[mb] += __shfl_xor_sync(0xffffffffu, pb[mb], 1);
            pb[mb] += __shfl_xor_sync(0xffffffffu, pb[mb], 2);
        }
        float* red = (float*)(sm + OFFS_OFF);   // offs no longer needed
        __syncthreads();                        // all sampling reads of offs are done
        if ((lid & 3) == 0) {
            #pragma unroll
            for (int mb = 0; mb < 2; mb++) {
                int row = mwarp*32 + mb*16 + (lid >> 2);
                red[nwarp*128 + row]     = pa[mb];
                red[nwarp*128 + row + 8] = pb[mb];
            }
        }
        __syncthreads();
        if (t < 128) out_f[p0 + t] = red[t] + red[128 + t] + b1x1[0];
    }
}

// ---------------- launch -----------------------------------------------------
extern "C" void kernel_launch(void* const* d_in, const int* in_sizes, int n_in,
                              void* d_out, int out_size) {
    const float* x    = (const float*)d_in[0];
    const float* w1o  = (const float*)d_in[1];
    const float* b1o  = (const float*)d_in[2];
    const float* wd1  = (const float*)d_in[3];
    const float* db1  = (const float*)d_in[4];
    const float* g1   = (const float*)d_in[5];
    const float* be1  = (const float*)d_in[6];
    const float* m1   = (const float*)d_in[7];
    const float* v1   = (const float*)d_in[8];
    const float* w2o  = (const float*)d_in[9];
    const float* b2o  = (const float*)d_in[10];
    const float* wd2  = (const float*)d_in[11];
    const float* db2  = (const float*)d_in[12];
    const float* g2   = (const float*)d_in[13];
    const float* be2  = (const float*)d_in[14];
    const float* m2   = (const float*)d_in[15];
    const float* v2   = (const float*)d_in[16];
    const float* wc   = (const float*)d_in[17];
    const float* bc   = (const float*)d_in[18];
    float* out = (float*)d_out;

    cudaFuncSetAttribute(layer_kernel<0>, cudaFuncAttributeMaxDynamicSharedMemorySize, LAYER_SMEM);
    cudaFuncSetAttribute(layer_kernel<1>, cudaFuncAttributeMaxDynamicSharedMemorySize, LAYER_SMEM);

    prep_kernel<<<64, 256>>>(w1o, w2o, wd1, wd2, db1, db2,
                             g1, be1, m1, v1, g2, be2, m2, v2);
    transpose_kernel<<<4096 + 21, 256>>>(x);
    layer_kernel<0><<<2048, 256, LAYER_SMEM>>>(0, b1o, nullptr, nullptr, nullptr);
    layer_kernel<1><<<2048, 256, LAYER_SMEM>>>(1, b2o, wc, bc, out);
}

// round 17
// speedup vs baseline: 1.0445x; 1.0445x over previous
#include <cuda_runtime.h>
#include <cuda_fp16.h>
#include <math.h>
#include <stdint.h>

#define HH 512
#define WW 512
#define NP (HH*WW)
#define PW 517                      // padded dim (2 left/top, 3 right/bottom)

// ---------------- scratch (device globals) ---------------------------------
__device__ __align__(16) __half g_xp[PW*PW*64];        // input NHWC fp16, zero-padded
__device__ __align__(16) __half g_h1p[PW*PW*64];       // layer-1 out NHWC fp16, zero-padded
__device__ __align__(16) __half g_wdb[2][9][64*64];    // dcn W fp16: [layer][tap][SWZ(c*128+oc*2)]
__device__ __align__(16) __half g_wob[2][9][32*64];    // off W fp16, 32 oc, 64B rows, SW64
__device__ float g_bnscale[2][64];
__device__ float g_bnshift[2][64];

// ---------------- smem layout (bytes) ----------------------------------------
#define SLAB_PX   130
#define P1_B0     50176            // 4 x 4KB ring (taps)
#define P2_A0     0
#define P2_A1     16384
#define P2_B0     32768
#define P2_B1     40960
#define OFFS_OFF  66560            // offs (9216B); doubles as tap-8 B before epilogue
#define LAYER_SMEM 75776

// ---------------- helpers ----------------------------------------------------
__device__ __forceinline__ uint32_t smem_u32(const void* p) {
    uint32_t a;
    asm("{ .reg .u64 t; cvta.to.shared.u64 t, %1; cvt.u32.u64 %0, t; }" : "=r"(a) : "l"(p));
    return a;
}
#define SWZ(b)   ((b) ^ (((b) >> 3) & 0x70))
#define SWZ64(b) ((b) ^ (((b) >> 3) & 0x30))

#define CP_ASYNC16(dst, src) \
    asm volatile("cp.async.cg.shared.global [%0], [%1], 16;" :: "r"(dst), "l"(src))
#define CP_COMMIT()  asm volatile("cp.async.commit_group;")
#define CP_WAIT0()   asm volatile("cp.async.wait_group 0;")

#define LDSM4(r, addr) \
    asm volatile("ldmatrix.sync.aligned.m8n8.x4.shared.b16 {%0,%1,%2,%3}, [%4];" \
        : "=r"((r)[0]), "=r"((r)[1]), "=r"((r)[2]), "=r"((r)[3]) : "r"(addr))
#define LDSM4T(r, addr) \
    asm volatile("ldmatrix.sync.aligned.m8n8.x4.trans.shared.b16 {%0,%1,%2,%3}, [%4];" \
        : "=r"((r)[0]), "=r"((r)[1]), "=r"((r)[2]), "=r"((r)[3]) : "r"(addr))
#define MMA(d, a, b0_, b1_) \
    asm volatile("mma.sync.aligned.m16n8k16.row.col.f32.f16.f16.f32 " \
        "{%0,%1,%2,%3}, {%4,%5,%6,%7}, {%8,%9}, {%0,%1,%2,%3};" \
        : "+f"((d)[0]), "+f"((d)[1]), "+f"((d)[2]), "+f"((d)[3]) \
        : "r"((a)[0]), "r"((a)[1]), "r"((a)[2]), "r"((a)[3]), "r"(b0_), "r"(b1_))

// ---------------- GEMM one tap (dcn, 4M x 2N warps, single-pass B, 64 oc) ---
__device__ __forceinline__ void gemm_tap_dcn(uint32_t sAb, uint32_t sBb, int lid,
                                             int mwarp, int nwarp, float acc[2][4][4]) {
    #pragma unroll
    for (int kb = 0; kb < 4; kb++) {
        uint32_t ah[2][4];
        #pragma unroll
        for (int mb = 0; mb < 2; mb++) {
            int row = mwarp*32 + mb*16 + (lid & 15);
            uint32_t a = sAb + SWZ((uint32_t)(row*128 + (kb*16 + (lid>>4)*8)*2));
            LDSM4(ah[mb], a);
        }
        #pragma unroll
        for (int nb2 = 0; nb2 < 2; nb2++) {
            int k = kb*16 + (lid & 15);
            int n = nwarp*32 + nb2*16 + (lid>>4)*8;
            uint32_t b = sBb + SWZ((uint32_t)(k*128 + n*2));
            uint32_t bh[4];
            LDSM4T(bh, b);
            #pragma unroll
            for (int mb = 0; mb < 2; mb++) {
                MMA(acc[mb][2*nb2],   ah[mb], bh[0], bh[1]);
                MMA(acc[mb][2*nb2+1], ah[mb], bh[2], bh[3]);
            }
        }
    }
}

// ---------------- GEMM one tap (offconv from slab, 32 oc, SW64 B) -----------
__device__ __forceinline__ void gemm_tap_off_slab(uint32_t sbase, int ky, int kx,
                                                  uint32_t sBb, int lid,
                                                  int mwarp, int nwarp, float acc[2][2][4]) {
    const int srbase = ky*SLAB_PX + kx;
    #pragma unroll
    for (int kb = 0; kb < 4; kb++) {
        uint32_t ah[2][4];
        #pragma unroll
        for (int mb = 0; mb < 2; mb++) {
            int row = srbase + mwarp*32 + mb*16 + (lid & 15);
            uint32_t a = sbase + SWZ((uint32_t)(row*128 + (kb*16 + (lid>>4)*8)*2));
            LDSM4(ah[mb], a);
        }
        int k = kb*16 + (lid & 15);
        int n = nwarp*16 + (lid>>4)*8;
        uint32_t b = sBb + SWZ64((uint32_t)(k*64 + n*2));
        uint32_t bh[4];
        LDSM4T(bh, b);
        #pragma unroll
        for (int mb = 0; mb < 2; mb++) {
            MMA(acc[mb][0], ah[mb], bh[0], bh[1]);
            MMA(acc[mb][1], ah[mb], bh[2], bh[3]);
        }
    }
}

// stage dcn tap weights (8KB fp16) via cp.async
__device__ __forceinline__ void stage_b8(const __half* __restrict__ wsrc, int k,
                                         uint32_t sBb, int t) {
    const char* src = (const char*)(wsrc + (size_t)k * 4096);
    #pragma unroll
    for (int i = 0; i < 2; i++)
        CP_ASYNC16(sBb + (uint32_t)(i*256 + t)*16, src + (size_t)(i*256 + t)*16);
}
// stage offconv tap weights (4KB fp16) via cp.async — one 16B per thread
__device__ __forceinline__ void stage_b4(const __half* __restrict__ wsrc, int k,
                                         uint32_t sBb, int t) {
    const char* src = (const char*)(wsrc + (size_t)k * 2048);
    CP_ASYNC16(sBb + (uint32_t)t*16, src + (size_t)t*16);
}

// stage the 3x130-pixel input slab, swizzled (48.75KB) via cp.async
__device__ __forceinline__ void stage_slab(const __half* __restrict__ in,
                                           int by, int x0, uint32_t sbase, int t) {
    for (int idx = t; idx < 3*SLAB_PX*8; idx += 256) {
        int pix = idx >> 3, sub = idx & 7;
        int r = pix / SLAB_PX, p = pix % SLAB_PX;
        const char* src = (const char*)(in + ((size_t)((by+1+r)*PW + (x0+1+p)))*64) + sub*16;
        uint32_t dst = sbase + SWZ((uint32_t)((r*SLAB_PX + p)*128 + sub*16));
        CP_ASYNC16(dst, src);
    }
}

// bilinear sample one tap from fp16 padded input; 8 lanes/pixel, 16B/lane
__device__ __forceinline__ void sample_dcn(const __half* __restrict__ in,
                                           const float* __restrict__ offs,
                                           int by, int x0, int k,
                                           char* sm, uint32_t abuf,
                                           const int* pxv, const uint32_t* aoff,
                                           int ch8) {
    int ky = k/3 - 1, kx = k%3 - 1;
    #pragma unroll
    for (int it = 0; it < 4; it++) {
        int px = pxv[it];
        float2 od = *(const float2*)(offs + px*18 + 2*k);
        float py  = (float)(by + ky) + od.x;
        float pxf = (float)(x0 + px + kx) + od.y;
        float fy = floorf(py), fx = floorf(pxf);
        float wy = py - fy, wx = pxf - fx;
        int yi = min(max((int)fy, -2), 513);
        int xi = min(max((int)fx, -2), 513);
        float w00 = (1.f - wy)*(1.f - wx);
        float w01 = (1.f - wy)*wx;
        float w10 = wy*(1.f - wx);
        float w11 = wy*wx;
        const __half* b00 = in + ((size_t)((yi+2)*PW + (xi+2)))*64 + ch8*8;
        const __half* b10 = b00 + (size_t)PW*64;
        uint4 r00 = *(const uint4*)b00;
        uint4 r01 = *(const uint4*)(b00 + 64);
        uint4 r10 = *(const uint4*)b10;
        uint4 r11 = *(const uint4*)(b10 + 64);
        uint4 outv;
        const uint32_t* p00 = &r00.x;
        const uint32_t* p01 = &r01.x;
        const uint32_t* p10 = &r10.x;
        const uint32_t* p11 = &r11.x;
        uint32_t* po = &outv.x;
        #pragma unroll
        for (int j = 0; j < 4; j++) {
            float2 f00 = __half22float2(*(const __half2*)&p00[j]);
            float2 f01 = __half22float2(*(const __half2*)&p01[j]);
            float2 f10 = __half22float2(*(const __half2*)&p10[j]);
            float2 f11 = __half22float2(*(const __half2*)&p11[j]);
            float sx = w00*f00.x + w01*f01.x + w10*f10.x + w11*f11.x;
            float sy = w00*f00.y + w01*f01.y + w10*f10.y + w11*f11.y;
            __half2 h = __floats2half2_rn(sx, sy);
            po[j] = *(const uint32_t*)&h;
        }
        *(uint4*)(sm + abuf + aoff[it]) = outv;
    }
}

// ---------------- prep: weight swizzle + BN folding --------------------------
__global__ void prep_kernel(
    const float* __restrict__ w1o, const float* __restrict__ w2o,
    const float* __restrict__ wd1, const float* __restrict__ wd2,
    const float* __restrict__ db1, const float* __restrict__ db2,
    const float* __restrict__ g1, const float* __restrict__ b1,
    const float* __restrict__ m1, const float* __restrict__ v1,
    const float* __restrict__ g2, const float* __restrict__ b2,
    const float* __restrict__ m2, const float* __restrict__ v2)
{
    int idx = blockIdx.x * blockDim.x + threadIdx.x;
    int nth = gridDim.x * blockDim.x;
    for (int i = idx; i < 2*9*64*64; i += nth) {
        int layer = i / 36864, r = i % 36864;
        int k = r / 4096, rr = r & 4095;
        int c = rr >> 6, oc = rr & 63;
        {
            uint32_t sidx = SWZ((uint32_t)(c*128 + oc*2)) >> 1;
            float val = (layer ? wd2 : wd1)[(oc*64 + c)*9 + k];
            g_wdb[layer][k][sidx] = __float2half_rn(val);
        }
        if (oc < 32) {
            uint32_t sidx = SWZ64((uint32_t)(c*64 + oc*2)) >> 1;
            float val = (oc < 18) ? (layer ? w2o : w1o)[(oc*64 + c)*9 + k] : 0.f;
            g_wob[layer][k][sidx] = __float2half_rn(val);
        }
    }
    if (idx < 64) {
        float s = g1[idx] * rsqrtf(v1[idx] + 1e-5f);
        g_bnscale[0][idx] = s;
        g_bnshift[0][idx] = b1[idx] - m1[idx]*s + db1[idx]*s;
        float s2 = g2[idx] * rsqrtf(v2[idx] + 1e-5f);
        g_bnscale[1][idx] = s2;
        g_bnshift[1][idx] = b2[idx] - m2[idx]*s2 + db2[idx]*s2;
    }
}

// ---------------- NCHW f32 -> padded NHWC fp16 (+border zeroing) -------------
__global__ void __launch_bounds__(256) transpose_kernel(const float* __restrict__ x) {
    __shared__ float tile[64][65];
    int b = blockIdx.x;
    int t = threadIdx.x;
    if (b >= 4096) {
        int idx = (b - 4096)*256 + t;
        if (idx >= 5145) return;
        int r, c;
        if (idx < 2585) {                   // 5 full rows: 0,1,514,515,516
            int rr = idx / 517;
            r = (rr < 2) ? rr : (512 + rr);
            c = idx % 517;
        } else {
            int j = idx - 2585;
            r = 2 + j / 5;
            int jc = j % 5;
            c = (jc < 2) ? jc : (512 + jc);
        }
        uint4 z = make_uint4(0u, 0u, 0u, 0u);
        uint4* p0 = (uint4*)(g_xp  + ((size_t)(r*PW + c))*64);
        uint4* p1 = (uint4*)(g_h1p + ((size_t)(r*PW + c))*64);
        #pragma unroll
        for (int i = 0; i < 8; i++) { p0[i] = z; p1[i] = z; }
        return;
    }
    int p0 = b * 64;
    #pragma unroll
    for (int i = 0; i < 16; i++) {
        int idx = i*256 + t;
        int c = idx >> 6, pl = idx & 63;
        tile[c][pl] = x[c*NP + p0 + pl];
    }
    __syncthreads();
    int y = p0 / WW, xb = p0 % WW;
    __half* dst = g_xp + ((size_t)((y+2)*PW + xb + 2))*64;
    #pragma unroll
    for (int i = 0; i < 8; i++) {
        int idx = i*512 + t*2;          // pairs of channels
        int pl = idx >> 6, c = idx & 63;
        __half2 h = __floats2half2_rn(tile[c][pl], tile[c+1][pl]);
        *(__half2*)(dst + (size_t)pl*64 + c) = h;
    }
}

// ---------------- fused layer: offconv(slab) -> deform conv -> BN/ReLU (+1x1)
template<int FUSE>
__global__ void __launch_bounds__(256, 3) layer_kernel(int layer,
    const float* __restrict__ obias,
    const float* __restrict__ w1x1, const float* __restrict__ b1x1,
    float* __restrict__ out_f)
{
    extern __shared__ char sm[];
    const uint32_t sbase = smem_u32(sm);
    float* offs = (float*)(sm + OFFS_OFF);
    const __half* __restrict__ in = layer ? g_h1p : g_xp;
    const __half* __restrict__ wo = &g_wob[layer][0][0];
    const __half* __restrict__ wd = &g_wdb[layer][0][0];
    const float* __restrict__ scl = g_bnscale[layer];
    const float* __restrict__ shf = g_bnshift[layer];
    const int t = threadIdx.x;
    const int wid = t >> 5, lid = t & 31;
    const int mwarp = wid & 3, nwarp = wid >> 2;
    const int by = blockIdx.x >> 2;
    const int x0 = (blockIdx.x & 3) * 128;
    const int p0 = by*WW + x0;
    const int ch8 = lid & 7;
    const int pxq = lid >> 3;

    int pxv[4];
    uint32_t aoff[4];
    #pragma unroll
    for (int it = 0; it < 4; it++) {
        pxv[it] = it*32 + wid*4 + pxq;
        aoff[it] = SWZ((uint32_t)(pxv[it]*128 + ch8*16));
    }

    // ================= phase 1: offset conv from input slab =================
    {
        stage_slab(in, by, x0, sbase, t);
        #pragma unroll
        for (int j = 0; j < 4; j++)
            stage_b4(wo, j, sbase + P1_B0 + j*4096, t);
        CP_COMMIT();
        CP_WAIT0();
        __syncthreads();

        float acc[2][2][4] = {};
        #pragma unroll
        for (int k = 0; k < 4; k++)
            gemm_tap_off_slab(sbase, k/3, k%3, sbase + P1_B0 + k*4096,
                              lid, mwarp, nwarp, acc);
        __syncthreads();                 // B ring free for reuse
        #pragma unroll
        for (int j = 0; j < 4; j++)
            stage_b4(wo, 4 + j, sbase + P1_B0 + j*4096, t);
        stage_b4(wo, 8, sbase + OFFS_OFF, t);   // 5th tile parks in offs region
        CP_COMMIT();
        CP_WAIT0();
        __syncthreads();
        #pragma unroll
        for (int k = 4; k < 8; k++)
            gemm_tap_off_slab(sbase, k/3, k%3, sbase + P1_B0 + (k-4)*4096,
                              lid, mwarp, nwarp, acc);
        gemm_tap_off_slab(sbase, 2, 2, sbase + OFFS_OFF, lid, mwarp, nwarp, acc);
        __syncthreads();                 // slab + all B reads done
        // overlap: stage phase-2 tap-0 B into the now-dead slab region
        stage_b8(wd, 0, sbase + P2_B0, t);
        CP_COMMIT();
        // epilogue -> smem offs (with bias); overwrites parked tap-8 B (dead)
        #pragma unroll
        for (int mb = 0; mb < 2; mb++) {
            int row = mwarp*32 + mb*16 + (lid >> 2);
            #pragma unroll
            for (int nb = 0; nb < 2; nb++) {
                int colb = nwarp*16 + nb*8 + (lid & 3)*2;
                if (colb < 18) {
                    float b0 = obias[colb], b1v = obias[colb+1];
                    offs[row*18 + colb]         = acc[mb][nb][0] + b0;
                    offs[row*18 + colb + 1]     = acc[mb][nb][1] + b1v;
                    offs[(row+8)*18 + colb]     = acc[mb][nb][2] + b0;
                    offs[(row+8)*18 + colb + 1] = acc[mb][nb][3] + b1v;
                }
            }
        }
        __syncthreads();
    }

    // ================= phase 2: deformable conv (single-pass B) =============
    sample_dcn(in, offs, by, x0, 0, sm, P2_A0, pxv, aoff, ch8);
    CP_WAIT0();
    __syncthreads();

    float acc[2][4][4] = {};
    for (int k = 0; k < 9; k++) {
        uint32_t cab = (k & 1) ? P2_A1 : P2_A0;
        uint32_t cbb = (k & 1) ? P2_B1 : P2_B0;
        if (k < 8) {
            uint32_t nab = (k & 1) ? P2_A0 : P2_A1;
            uint32_t nbb = (k & 1) ? P2_B0 : P2_B1;
            stage_b8(wd, k+1, sbase + nbb, t);
            CP_COMMIT();
            sample_dcn(in, offs, by, x0, k+1, sm, nab, pxv, aoff, ch8);
        }
        gemm_tap_dcn(sbase + cab, sbase + cbb, lid, mwarp, nwarp, acc);
        CP_WAIT0();
        __syncthreads();
    }

    if (!FUSE) {
        __half* dstbase = g_h1p + ((size_t)((by+2)*PW + x0 + 2))*64;
        #pragma unroll
        for (int mb = 0; mb < 2; mb++) {
            int row = mwarp*32 + mb*16 + (lid >> 2);
            #pragma unroll
            for (int nb = 0; nb < 4; nb++) {
                int colb = nwarp*32 + nb*8 + (lid & 3)*2;
                float s0 = scl[colb], s1 = scl[colb+1];
                float h0 = shf[colb], h1v = shf[colb+1];
                float v00 = fmaxf(acc[mb][nb][0]*s0 + h0, 0.f);
                float v01 = fmaxf(acc[mb][nb][1]*s1 + h1v, 0.f);
                float v10 = fmaxf(acc[mb][nb][2]*s0 + h0, 0.f);
                float v11 = fmaxf(acc[mb][nb][3]*s1 + h1v, 0.f);
                *(__half2*)(dstbase + (size_t)row*64 + colb)       = __floats2half2_rn(v00, v01);
                *(__half2*)(dstbase + (size_t)(row + 8)*64 + colb) = __floats2half2_rn(v10, v11);
            }
        }
    } else {
        float pa[2] = {0.f, 0.f}, pb[2] = {0.f, 0.f};
        #pragma unroll
        for (int mb = 0; mb < 2; mb++) {
            #pragma unroll
            for (int nb = 0; nb < 4; nb++) {
                int colb = nwarp*32 + nb*8 + (lid & 3)*2;
                float s0 = scl[colb], s1 = scl[colb+1];
                float h0 = shf[colb], h1v = shf[colb+1];
                float w0 = w1x1[colb], w1 = w1x1[colb+1];
                float v00 = fmaxf(acc[mb][nb][0]*s0 + h0, 0.f);
                float v01 = fmaxf(acc[mb][nb][1]*s1 + h1v, 0.f);
                float v10 = fmaxf(acc[mb][nb][2]*s0 + h0, 0.f);
                float v11 = fmaxf(acc[mb][nb][3]*s1 + h1v, 0.f);
                pa[mb] += v00*w0 + v01*w1;
                pb[mb] += v10*w0 + v11*w1;
            }
            pa[mb] += __shfl_xor_sync(0xffffffffu, pa[mb], 1);
            pa[mb] += __shfl_xor_sync(0xffffffffu, pa[mb], 2);
            pb[mb] += __shfl_xor_sync(0xffffffffu, pb[mb], 1);
            pb[mb] += __shfl_xor_sync(0xffffffffu, pb[mb], 2);
        }
        float* red = (float*)(sm + OFFS_OFF);   // offs no longer needed
        __syncthreads();                        // all sampling reads of offs are done
        if ((lid & 3) == 0) {
            #pragma unroll
            for (int mb = 0; mb < 2; mb++) {
                int row = mwarp*32 + mb*16 + (lid >> 2);
                red[nwarp*128 + row]     = pa[mb];
                red[nwarp*128 + row + 8] = pb[mb];
            }
        }
        __syncthreads();
        if (t < 128) out_f[p0 + t] = red[t] + red[128 + t] + b1x1[0];
    }
}

// ---------------- launch -----------------------------------------------------
extern "C" void kernel_launch(void* const* d_in, const int* in_sizes, int n_in,
                              void* d_out, int out_size) {
    const float* x    = (const float*)d_in[0];
    const float* w1o  = (const float*)d_in[1];
    const float* b1o  = (const float*)d_in[2];
    const float* wd1  = (const float*)d_in[3];
    const float* db1  = (const float*)d_in[4];
    const float* g1   = (const float*)d_in[5];
    const float* be1  = (const float*)d_in[6];
    const float* m1   = (const float*)d_in[7];
    const float* v1   = (const float*)d_in[8];
    const float* w2o  = (const float*)d_in[9];
    const float* b2o  = (const float*)d_in[10];
    const float* wd2  = (const float*)d_in[11];
    const float* db2  = (const float*)d_in[12];
    const float* g2   = (const float*)d_in[13];
    const float* be2  = (const float*)d_in[14];
    const float* m2   = (const float*)d_in[15];
    const float* v2   = (const float*)d_in[16];
    const float* wc   = (const float*)d_in[17];
    const float* bc   = (const float*)d_in[18];
    float* out = (float*)d_out;

    cudaFuncSetAttribute(layer_kernel<0>, cudaFuncAttributeMaxDynamicSharedMemorySize, LAYER_SMEM);
    cudaFuncSetAttribute(layer_kernel<1>, cudaFuncAttributeMaxDynamicSharedMemorySize, LAYER_SMEM);

    prep_kernel<<<64, 256>>>(w1o, w2o, wd1, wd2, db1, db2,
                             g1, be1, m1, v1, g2, be2, m2, v2);
    transpose_kernel<<<4096 + 21, 256>>>(x);
    layer_kernel<0><<<2048, 256, LAYER_SMEM>>>(0, b1o, nullptr, nullptr, nullptr);
    layer_kernel<1><<<2048, 256, LAYER_SMEM>>>(1, b2o, wc, bc, out);
}